// round 4
// baseline (speedup 1.0000x reference)
#include <cuda_runtime.h>

#define M_TOTAL 16384   // 16 * 1024 queries
#define N_CODES 8192
#define DIMC    256
#define QUANT_ELEMS (M_TOTAL * DIMC)

// ---- scratch (no device allocation allowed) ----
__device__ float g_esq[N_CODES];
__device__ float g_qsq[M_TOTAL];
__device__ int   g_idx[M_TOTAL];
__device__ float g_loss;

// ============================================================
// Kernel A: row squared-norms (one warp per 256-float row).
// which==0 -> write g_esq (embedding rows), also zero g_loss.
// which==1 -> write g_qsq (query rows).
// Destination chosen INSIDE device code (device symbols must not
// be passed as kernel args from host).
// ============================================================
__global__ void rowsq_kernel(const float* __restrict__ src, int nrows, int which) {
    if (which == 0 && blockIdx.x == 0 && threadIdx.x == 0) g_loss = 0.0f;
    float* dst = which ? g_qsq : g_esq;
    int warp = (blockIdx.x * blockDim.x + threadIdx.x) >> 5;
    int lane = threadIdx.x & 31;
    if (warp >= nrows) return;
    const float4* row = (const float4*)(src + (size_t)warp * DIMC);
    float s = 0.0f;
    #pragma unroll
    for (int i = 0; i < 2; i++) {
        float4 v = row[lane + 32 * i];
        s += v.x * v.x + v.y * v.y + v.z * v.z + v.w * v.w;
    }
    #pragma unroll
    for (int o = 16; o > 0; o >>= 1) s += __shfl_xor_sync(0xFFFFFFFFu, s, o);
    if (lane == 0) dst[warp] = s;
}

// ============================================================
// Kernel B: fused distance-GEMM + argmin.
// CTA tile: 128 queries x 128 codes, K chunked by 32 through smem.
// 256 threads, 8x8 register tile each.
//
// Distance replicates the reference's fp32 rounding:
//   A = fl(q_sq + e_sq)
//   d = fl(A - 2*dot)   (fmaf(-2, dot, A); fl(2*dot)=2*dot exactly)
// Ties (ulp at |d|~256 is 3e-5, gaps can be smaller) break to the
// LOWEST index, matching jnp.argmin.
// ============================================================
#define MT 128
#define NT 128
#define KC 32

__global__ __launch_bounds__(256, 2)
void argmin_kernel(const float* __restrict__ Q, const float* __restrict__ E) {
    __shared__ float qs[KC][MT];   // 16 KB
    __shared__ float es[KC][NT];   // 16 KB

    const int tid = threadIdx.x;
    const int tx = tid & 15;       // code-column group (8 cols)
    const int ty = tid >> 4;       // query-row group (8 rows)
    const int m0 = blockIdx.x * MT;

    float qsq_r[8];
    #pragma unroll
    for (int i = 0; i < 8; i++) qsq_r[i] = g_qsq[m0 + ty * 8 + i];

    float minv[8];
    int   mini[8];
    #pragma unroll
    for (int i = 0; i < 8; i++) { minv[i] = 3.4e38f; mini[i] = 0; }

    for (int n0 = 0; n0 < N_CODES; n0 += NT) {
        float acc[8][8];
        #pragma unroll
        for (int i = 0; i < 8; i++)
            #pragma unroll
            for (int j = 0; j < 8; j++) acc[i][j] = 0.0f;

        for (int k0 = 0; k0 < DIMC; k0 += KC) {
            // cooperative load: 128 rows x 32 cols each for Q-tile and E-tile
            #pragma unroll
            for (int it = 0; it < 4; it++) {
                int f4 = tid + 256 * it;   // 0..1023
                int r  = f4 >> 3;          // row 0..127
                int c4 = f4 & 7;           // float4 column 0..7
                float4 v = *(const float4*)(Q + (size_t)(m0 + r) * DIMC + k0 + c4 * 4);
                qs[c4 * 4 + 0][r] = v.x; qs[c4 * 4 + 1][r] = v.y;
                qs[c4 * 4 + 2][r] = v.z; qs[c4 * 4 + 3][r] = v.w;
                float4 w = *(const float4*)(E + (size_t)(n0 + r) * DIMC + k0 + c4 * 4);
                es[c4 * 4 + 0][r] = w.x; es[c4 * 4 + 1][r] = w.y;
                es[c4 * 4 + 2][r] = w.z; es[c4 * 4 + 3][r] = w.w;
            }
            __syncthreads();

            #pragma unroll 8
            for (int kk = 0; kk < KC; kk++) {
                float4 a0 = *(const float4*)&qs[kk][ty * 8];
                float4 a1 = *(const float4*)&qs[kk][ty * 8 + 4];
                float4 b0 = *(const float4*)&es[kk][tx * 8];
                float4 b1 = *(const float4*)&es[kk][tx * 8 + 4];
                float a[8] = {a0.x, a0.y, a0.z, a0.w, a1.x, a1.y, a1.z, a1.w};
                float b[8] = {b0.x, b0.y, b0.z, b0.w, b1.x, b1.y, b1.z, b1.w};
                #pragma unroll
                for (int i = 0; i < 8; i++)
                    #pragma unroll
                    for (int j = 0; j < 8; j++)
                        acc[i][j] = fmaf(a[i], b[j], acc[i][j]);
            }
            __syncthreads();
        }

        // argmin update, ascending n within each thread (strict < keeps
        // the lowest tied index, matching jnp.argmin)
        #pragma unroll
        for (int j = 0; j < 8; j++) {
            int n = n0 + tx * 8 + j;
            float eq = __ldg(&g_esq[n]);
            #pragma unroll
            for (int i = 0; i < 8; i++) {
                float A = __fadd_rn(qsq_r[i], eq);      // fl(q_sq + e_sq)
                float d = fmaf(-2.0f, acc[i][j], A);    // fl(A - 2*dot)
                if (d < minv[i]) { minv[i] = d; mini[i] = n; }
            }
        }
    }

    // cross-thread reduction: 16 candidates per query row. Reuse qs/es smem.
    float* rv = &qs[0][0];
    int*   ri = (int*)&es[0][0];
    #pragma unroll
    for (int i = 0; i < 8; i++) {
        rv[(ty * 8 + i) * 16 + tx] = minv[i];
        ri[(ty * 8 + i) * 16 + tx] = mini[i];
    }
    __syncthreads();
    if (tid < MT) {
        float best = rv[tid * 16];
        int   bi   = ri[tid * 16];
        #pragma unroll
        for (int t = 1; t < 16; t++) {
            float v = rv[tid * 16 + t];
            int  id = ri[tid * 16 + t];
            if (v < best || (v == best && id < bi)) { best = v; bi = id; }
        }
        g_idx[m0 + tid] = bi;
    }
}

// ============================================================
// Kernel C: gather quantized vectors, write indices + ST output,
// accumulate sum of (q - e)^2 for the loss. One block per query.
// ============================================================
__global__ void gather_kernel(const float* __restrict__ Q,
                              const float* __restrict__ E,
                              float* __restrict__ out) {
    const int m = blockIdx.x;
    const int c = threadIdx.x;           // 256 threads = DIMC
    const int idx = g_idx[m];
    float q = Q[(size_t)m * DIMC + c];
    float e = E[(size_t)idx * DIMC + c];
    // straight-through, computed as the reference does: q + (e - q)
    out[M_TOTAL + (size_t)m * DIMC + c] = __fadd_rn(q, __fsub_rn(e, q));
    float d = q - e;
    float s = d * d;
    #pragma unroll
    for (int o = 16; o > 0; o >>= 1) s += __shfl_xor_sync(0xFFFFFFFFu, s, o);
    __shared__ float ws[8];
    int lane = c & 31, warp = c >> 5;
    if (lane == 0) ws[warp] = s;
    __syncthreads();
    if (c == 0) {
        float t = 0.0f;
        #pragma unroll
        for (int w = 0; w < 8; w++) t += ws[w];
        atomicAdd(&g_loss, t);
        out[m] = (float)idx;             // index output as float
    }
}

// ============================================================
// Kernel D: finalize vq_loss = 1.25 * mean((q - e)^2)
// ============================================================
__global__ void final_kernel(float* __restrict__ out) {
    out[M_TOTAL + (size_t)QUANT_ELEMS] = g_loss * 1.25f / (float)QUANT_ELEMS;
}

extern "C" void kernel_launch(void* const* d_in, const int* in_sizes, int n_in,
                              void* d_out, int out_size) {
    const float* Q = (const float*)d_in[0];   // [16,1024,256]
    const float* E = (const float*)d_in[1];   // [8192,256]
    float* out = (float*)d_out;

    rowsq_kernel<<<N_CODES / 8, 256>>>(E, N_CODES, 0);   // -> g_esq, zero g_loss
    rowsq_kernel<<<M_TOTAL / 8, 256>>>(Q, M_TOTAL, 1);   // -> g_qsq
    argmin_kernel<<<M_TOTAL / MT, 256>>>(Q, E);          // 128 CTAs
    gather_kernel<<<M_TOTAL, DIMC>>>(Q, E, out);         // 1 block / query
    final_kernel<<<1, 1>>>(out);
}